// round 1
// baseline (speedup 1.0000x reference)
#include <cuda_runtime.h>

#define B_    96
#define NW    10
#define NTOK  144
#define CH    192
#define HEADS_ 6
#define DH    32

#define SQS 37    // q/k smem row stride (odd-ish → conflict-free strided col reads)
#define SVS 36    // v smem row stride (float4-aligned)
#define SSS 145   // S smem row stride (145%32=17 odd → conflict-free)

// Scratch: qkv laid out [3, B, nW, H, N, Dh]; attention output [B, nW, N, C]
__device__ float g_qkv[(size_t)3 * B_ * NW * HEADS_ * NTOK * DH];   // ~318 MB
__device__ float g_att[(size_t)B_ * NW * NTOK * CH];                // ~106 MB

// ---------------------------------------------------------------------------
// GEMM1: qkv = x @ w_qkv + b_qkv, scatter epilogue into g_qkv
// A: [138240, 192], W: [192, 576]
// ---------------------------------------------------------------------------
__global__ __launch_bounds__(256) void qkv_gemm_kernel(
    const float* __restrict__ A, const float* __restrict__ W,
    const float* __restrict__ bias)
{
    const int BM = 128, BN = 64, BK = 16;
    __shared__ float As[16][132];
    __shared__ float Bs[16][64];
    int tid  = threadIdx.x;
    int row0 = blockIdx.x * BM;
    int col0 = blockIdx.y * BN;
    int ty = tid >> 4, tx = tid & 15;

    float acc[8][4];
#pragma unroll
    for (int i = 0; i < 8; i++)
#pragma unroll
        for (int j = 0; j < 4; j++) acc[i][j] = 0.f;

    for (int k0 = 0; k0 < CH; k0 += BK) {
#pragma unroll
        for (int l = 0; l < 2; l++) {
            int id = tid + l * 256;
            int r = id >> 2, c4 = (id & 3) << 2;
            float4 v = *(const float4*)(A + (size_t)(row0 + r) * CH + k0 + c4);
            As[c4 + 0][r] = v.x; As[c4 + 1][r] = v.y;
            As[c4 + 2][r] = v.z; As[c4 + 3][r] = v.w;
        }
        {
            int r = tid >> 4, c4 = (tid & 15) << 2;
            *(float4*)&Bs[r][c4] =
                *(const float4*)(W + (size_t)(k0 + r) * 576 + col0 + c4);
        }
        __syncthreads();
#pragma unroll
        for (int k = 0; k < BK; k++) {
            float a[8], b[4];
#pragma unroll
            for (int i = 0; i < 8; i++) a[i] = As[k][ty * 8 + i];
#pragma unroll
            for (int j = 0; j < 4; j++) b[j] = Bs[k][tx * 4 + j];
#pragma unroll
            for (int i = 0; i < 8; i++)
#pragma unroll
                for (int j = 0; j < 4; j++) acc[i][j] += a[i] * b[j];
        }
        __syncthreads();
    }

#pragma unroll
    for (int i = 0; i < 8; i++) {
        int m  = row0 + ty * 8 + i;
        int bw = m / NTOK, rr = m - bw * NTOK;
#pragma unroll
        for (int j = 0; j < 4; j++) {
            int n = col0 + tx * 4 + j;
            float v = acc[i][j] + bias[n];
            int t = n / CH; int rem = n - t * CH;
            int h = rem >> 5, d = rem & 31;
            g_qkv[((((size_t)t * (B_ * NW) + bw) * HEADS_ + h) * NTOK + rr) * DH + d] = v;
        }
    }
}

// ---------------------------------------------------------------------------
// GEMM2: out = g_att @ w_proj + b_proj   (A: [138240,192], W: [192,192])
// ---------------------------------------------------------------------------
__global__ __launch_bounds__(256) void proj_gemm_kernel(
    const float* __restrict__ W, const float* __restrict__ bias,
    float* __restrict__ out)
{
    const int BM = 128, BN = 64, BK = 16;
    __shared__ float As[16][132];
    __shared__ float Bs[16][64];
    int tid  = threadIdx.x;
    int row0 = blockIdx.x * BM;
    int col0 = blockIdx.y * BN;
    int ty = tid >> 4, tx = tid & 15;
    const float* A = g_att;

    float acc[8][4];
#pragma unroll
    for (int i = 0; i < 8; i++)
#pragma unroll
        for (int j = 0; j < 4; j++) acc[i][j] = 0.f;

    for (int k0 = 0; k0 < CH; k0 += BK) {
#pragma unroll
        for (int l = 0; l < 2; l++) {
            int id = tid + l * 256;
            int r = id >> 2, c4 = (id & 3) << 2;
            float4 v = *(const float4*)(A + (size_t)(row0 + r) * CH + k0 + c4);
            As[c4 + 0][r] = v.x; As[c4 + 1][r] = v.y;
            As[c4 + 2][r] = v.z; As[c4 + 3][r] = v.w;
        }
        {
            int r = tid >> 4, c4 = (tid & 15) << 2;
            *(float4*)&Bs[r][c4] =
                *(const float4*)(W + (size_t)(k0 + r) * CH + col0 + c4);
        }
        __syncthreads();
#pragma unroll
        for (int k = 0; k < BK; k++) {
            float a[8], b[4];
#pragma unroll
            for (int i = 0; i < 8; i++) a[i] = As[k][ty * 8 + i];
#pragma unroll
            for (int j = 0; j < 4; j++) b[j] = Bs[k][tx * 4 + j];
#pragma unroll
            for (int i = 0; i < 8; i++)
#pragma unroll
                for (int j = 0; j < 4; j++) acc[i][j] += a[i] * b[j];
        }
        __syncthreads();
    }

#pragma unroll
    for (int i = 0; i < 8; i++) {
        int m = row0 + ty * 8 + i;
#pragma unroll
        for (int j = 0; j < 4; j++) {
            int n = col0 + tx * 4 + j;
            out[(size_t)m * CH + n] = acc[i][j] + bias[n];
        }
    }
}

// ---------------------------------------------------------------------------
// Attention: one CTA per (b, w, h). 576 threads.
//   S = scale*Q@K^T + bias[w,h] + mask[b]; softmax rows; O = P@V -> g_att
// ---------------------------------------------------------------------------
__global__ __launch_bounds__(576, 1) void attn_kernel(
    const float* __restrict__ mask, const float* __restrict__ bias_table,
    const int* __restrict__ pidx)
{
    extern __shared__ float sm[];
    float* sq = sm;                    // [144][37]
    float* sk = sq + NTOK * SQS;       // [144][37]
    float* sv = sk + NTOK * SQS;       // [144][36]
    float* S  = sv + NTOK * SVS;       // [144][145]

    int tid = threadIdx.x;
    int h = blockIdx.x, w = blockIdx.y, b = blockIdx.z;

    size_t base = (((size_t)b * NW + w) * HEADS_ + h) * (NTOK * DH);
    const size_t seg = (size_t)(B_ * NW * HEADS_) * (NTOK * DH);
    const float* gq = g_qkv + base;
    const float* gk = gq + seg;
    const float* gv = gk + seg;

    for (int idx = tid; idx < NTOK * DH; idx += 576) {
        int r = idx >> 5, c = idx & 31;
        sq[r * SQS + c] = gq[idx];
        sk[r * SQS + c] = gk[idx];
        sv[r * SVS + c] = gv[idx];
    }
    __syncthreads();

    // ---- S = Q @ K^T with 6x6 per-thread register tiles (strided by 24) ----
    int tr = tid / 24;   // 0..23
    int tc = tid % 24;   // 0..23
    float acc[6][6];
#pragma unroll
    for (int i = 0; i < 6; i++)
#pragma unroll
        for (int j = 0; j < 6; j++) acc[i][j] = 0.f;

#pragma unroll 4
    for (int d = 0; d < DH; d++) {
        float a[6], kk[6];
#pragma unroll
        for (int u = 0; u < 6; u++) a[u]  = sq[(tr + 24 * u) * SQS + d];
#pragma unroll
        for (int u = 0; u < 6; u++) kk[u] = sk[(tc + 24 * u) * SQS + d];
#pragma unroll
        for (int i = 0; i < 6; i++)
#pragma unroll
            for (int j = 0; j < 6; j++) acc[i][j] += a[i] * kk[j];
    }

    const float scale = 0.17677669529663687f;   // 32^-0.5
    const float* mrow = mask + (size_t)b * NTOK * NTOK;
#pragma unroll
    for (int ui = 0; ui < 6; ui++) {
        int gi = tr + 24 * ui;
#pragma unroll
        for (int uj = 0; uj < 6; uj++) {
            int gj = tc + 24 * uj;
            int p = pidx[gi * NTOK + gj];
            float bv = bias_table[(p * NW + w) * HEADS_ + h];
            S[gi * SSS + gj] = acc[ui][uj] * scale + bv + mrow[gi * NTOK + gj];
        }
    }
    __syncthreads();

    // ---- row softmax: 18 warps, 8 rows each ----
    int warp = tid >> 5, lane = tid & 31;
    for (int r = warp; r < NTOK; r += 18) {
        float* Sr = S + r * SSS;
        float mx = -3.4e38f;
        for (int j = lane; j < NTOK; j += 32) mx = fmaxf(mx, Sr[j]);
#pragma unroll
        for (int o = 16; o > 0; o >>= 1)
            mx = fmaxf(mx, __shfl_xor_sync(0xffffffffu, mx, o));
        float s = 0.f;
        for (int j = lane; j < NTOK; j += 32) {
            float e = __expf(Sr[j] - mx);
            Sr[j] = e;
            s += e;
        }
#pragma unroll
        for (int o = 16; o > 0; o >>= 1)
            s += __shfl_xor_sync(0xffffffffu, s, o);
        float inv = 1.f / s;
        for (int j = lane; j < NTOK; j += 32) Sr[j] *= inv;
    }
    __syncthreads();

    // ---- O = P @ V : thread = (row, 8-wide d chunk) ----
    int r  = tid >> 2;          // 0..143
    int d0 = (tid & 3) << 3;    // 0,8,16,24
    float o0 = 0.f, o1 = 0.f, o2 = 0.f, o3 = 0.f;
    float o4 = 0.f, o5 = 0.f, o6 = 0.f, o7 = 0.f;
#pragma unroll 4
    for (int j = 0; j < NTOK; j++) {
        float p = S[r * SSS + j];
        float4 v0 = *(const float4*)&sv[j * SVS + d0];
        float4 v1 = *(const float4*)&sv[j * SVS + d0 + 4];
        o0 += p * v0.x; o1 += p * v0.y; o2 += p * v0.z; o3 += p * v0.w;
        o4 += p * v1.x; o5 += p * v1.y; o6 += p * v1.z; o7 += p * v1.w;
    }
    float* op = g_att + ((((size_t)b * NW + w) * NTOK + r) * CH) + h * DH + d0;
    float4 w0 = make_float4(o0, o1, o2, o3);
    float4 w1 = make_float4(o4, o5, o6, o7);
    *(float4*)op       = w0;
    *(float4*)(op + 4) = w1;
}

// ---------------------------------------------------------------------------
extern "C" void kernel_launch(void* const* d_in, const int* in_sizes, int n_in,
                              void* d_out, int out_size)
{
    const float* x          = (const float*)d_in[0];
    const float* mask       = (const float*)d_in[1];
    const float* w_qkv      = (const float*)d_in[2];
    const float* b_qkv      = (const float*)d_in[3];
    const float* w_proj     = (const float*)d_in[4];
    const float* b_proj     = (const float*)d_in[5];
    const float* bias_table = (const float*)d_in[6];
    const int*   pidx       = (const int*)d_in[7];
    float* out = (float*)d_out;

    const size_t smem_bytes =
        (size_t)(NTOK * SQS * 2 + NTOK * SVS + NTOK * SSS) * sizeof(float); // 146880
    cudaFuncSetAttribute(attn_kernel,
                         cudaFuncAttributeMaxDynamicSharedMemorySize,
                         (int)smem_bytes);

    // 1) QKV projection GEMM: M=138240 (=1080*128), N=576 (=9*64)
    qkv_gemm_kernel<<<dim3(1080, 9), 256>>>(x, w_qkv, b_qkv);

    // 2) Fused window attention: one CTA per (b, w, h)
    attn_kernel<<<dim3(HEADS_, NW, B_), 576, smem_bytes>>>(mask, bias_table, pidx);

    // 3) Output projection GEMM: N=192 (=3*64)
    proj_gemm_kernel<<<dim3(1080, 3), 256>>>(w_proj, b_proj, out);
}

// round 3
// speedup vs baseline: 2.0047x; 2.0047x over previous
#include <cuda_runtime.h>
#include <cstdint>

#define B_    96
#define NW    10
#define NTOK  144
#define CH    192
#define HEADS_ 6
#define DH    32

#define SQS 37
#define SVS 36
#define SSS 145

// GEMM tiling
#define BM 128
#define BN 64
#define BK 32
#define ASTR 36   // As row stride (floats): 144B rows, 16B-aligned, conflict-free ldmatrix
#define BSTR 68   // Bs row stride (floats)

// Scratch
__device__ float g_qkv[(size_t)3 * B_ * NW * HEADS_ * NTOK * DH];
__device__ float g_att[(size_t)B_ * NW * NTOK * CH];

// ---------------------------------------------------------------------------
// helpers
// ---------------------------------------------------------------------------
__device__ __forceinline__ uint32_t smem_u32(const void* p) {
    uint32_t a;
    asm("{ .reg .u64 t; cvta.to.shared.u64 t, %1; cvt.u32.u64 %0, t; }"
        : "=r"(a) : "l"(p));
    return a;
}
__device__ __forceinline__ float f2tf32(float x) {
    uint32_t r;
    asm("cvt.rna.tf32.f32 %0, %1;" : "=r"(r) : "f"(x));
    return __uint_as_float(r);
}
__device__ __forceinline__ void ldmA(uint32_t a[4], uint32_t addr) {
    asm volatile("ldmatrix.sync.aligned.m8n8.x4.shared.b16 {%0,%1,%2,%3}, [%4];"
                 : "=r"(a[0]), "=r"(a[1]), "=r"(a[2]), "=r"(a[3]) : "r"(addr));
}
__device__ __forceinline__ void mma_tf32(float c[4], const uint32_t a[4],
                                         uint32_t b0, uint32_t b1) {
    asm volatile(
        "mma.sync.aligned.m16n8k8.row.col.f32.tf32.tf32.f32 "
        "{%0,%1,%2,%3},{%4,%5,%6,%7},{%8,%9},{%0,%1,%2,%3};"
        : "+f"(c[0]), "+f"(c[1]), "+f"(c[2]), "+f"(c[3])
        : "r"(a[0]), "r"(a[1]), "r"(a[2]), "r"(a[3]), "r"(b0), "r"(b1));
}

// ---------------------------------------------------------------------------
// tf32 tensor-core GEMM mainloop (acc += A[row0:+128, :] * W[:, col0:+64])
// A: [M,192] row-major fp32; W: [192, LDW] row-major fp32.
// 256 threads, 8 warps in 4x2 grid, 32x32 warp tiles.
// ---------------------------------------------------------------------------
template <int LDW>
__device__ __forceinline__ void gemm_tf32_main(
    const float* __restrict__ A, const float* __restrict__ W,
    int row0, int col0, float* As, float* Bs, float acc[2][4][4])
{
    int tid  = threadIdx.x;
    int warp = tid >> 5, lane = tid & 31;
    int wr = warp >> 1, wc = warp & 1;
    int mbase = wr * 32, nbase = wc * 32;
    int g = lane >> 2, la3 = lane & 3;

    // ldmatrix per-lane addresses for A (row-major [128][ASTR])
    int a_row = mbase + (lane & 15);
    int a_cs  = (lane >> 4) * 4;
    uint32_t aAddr0 = smem_u32(&As[a_row * ASTR + a_cs]);
    uint32_t aAddr1 = smem_u32(&As[(a_row + 16) * ASTR + a_cs]);

    for (int k0 = 0; k0 < CH; k0 += BK) {
        // As: 128 rows x 32 cols = 1024 float4 -> 4 iterations of 256 threads
#pragma unroll
        for (int l = 0; l < 4; l++) {
            int idx = tid + l * 256;
            int r = idx >> 3, c4 = (idx & 7) << 2;
            float4 v = *(const float4*)(A + (size_t)(row0 + r) * CH + k0 + c4);
            v.x = f2tf32(v.x); v.y = f2tf32(v.y);
            v.z = f2tf32(v.z); v.w = f2tf32(v.w);
            *(float4*)&As[r * ASTR + c4] = v;
        }
        // Bs: 32 rows x 64 cols = 512 float4 -> 2 iterations
#pragma unroll
        for (int l = 0; l < 2; l++) {
            int idx = tid + l * 256;
            int r = idx >> 4, c4 = (idx & 15) << 2;
            float4 v = *(const float4*)(W + (size_t)(k0 + r) * LDW + col0 + c4);
            v.x = f2tf32(v.x); v.y = f2tf32(v.y);
            v.z = f2tf32(v.z); v.w = f2tf32(v.w);
            *(float4*)&Bs[r * BSTR + c4] = v;
        }
        __syncthreads();

#pragma unroll
        for (int kc = 0; kc < BK; kc += 8) {
            uint32_t a0[4], a1[4];
            ldmA(a0, aAddr0 + kc * 4);
            ldmA(a1, aAddr1 + kc * 4);
            uint32_t b[4][2];
#pragma unroll
            for (int nr = 0; nr < 4; nr++) {
                int n = nbase + nr * 8 + g;
                b[nr][0] = __float_as_uint(Bs[(kc + la3) * BSTR + n]);
                b[nr][1] = __float_as_uint(Bs[(kc + 4 + la3) * BSTR + n]);
            }
#pragma unroll
            for (int nr = 0; nr < 4; nr++) {
                mma_tf32(acc[0][nr], a0, b[nr][0], b[nr][1]);
                mma_tf32(acc[1][nr], a1, b[nr][0], b[nr][1]);
            }
        }
        __syncthreads();
    }
}

// ---------------------------------------------------------------------------
// GEMM1: qkv = x @ w_qkv + b_qkv, scatter into g_qkv [3,B,nW,H,N,Dh]
// grid: (9, 1080) — N tiles fastest for A reuse in L2
// ---------------------------------------------------------------------------
__global__ __launch_bounds__(256) void qkv_gemm_mma(
    const float* __restrict__ A, const float* __restrict__ W,
    const float* __restrict__ bias)
{
    __shared__ float As[BM * ASTR];
    __shared__ float Bs[BK * BSTR];
    int row0 = blockIdx.y * BM;
    int col0 = blockIdx.x * BN;

    float acc[2][4][4];
#pragma unroll
    for (int m = 0; m < 2; m++)
#pragma unroll
        for (int n = 0; n < 4; n++)
#pragma unroll
            for (int j = 0; j < 4; j++) acc[m][n][j] = 0.f;

    gemm_tf32_main<576>(A, W, row0, col0, As, Bs, acc);

    int tid = threadIdx.x;
    int warp = tid >> 5, lane = tid & 31;
    int wr = warp >> 1, wc = warp & 1;
    int g = lane >> 2, la3 = lane & 3;

#pragma unroll
    for (int mr = 0; mr < 2; mr++) {
#pragma unroll
        for (int nr = 0; nr < 4; nr++) {
#pragma unroll
            for (int j = 0; j < 4; j++) {
                int row = row0 + wr * 32 + mr * 16 + g + ((j >> 1) << 3);
                int n   = col0 + wc * 32 + nr * 8 + la3 * 2 + (j & 1);
                float v = acc[mr][nr][j] + bias[n];
                int bw = row / NTOK, rr = row - bw * NTOK;
                int t = n / CH, rem = n - t * CH;
                int h = rem >> 5, d = rem & 31;
                g_qkv[((((size_t)t * (B_ * NW) + bw) * HEADS_ + h) * NTOK + rr) * DH + d] = v;
            }
        }
    }
}

// ---------------------------------------------------------------------------
// GEMM2: out = g_att @ w_proj + b_proj.  grid: (3, 1080)
// ---------------------------------------------------------------------------
__global__ __launch_bounds__(256) void proj_gemm_mma(
    const float* __restrict__ W, const float* __restrict__ bias,
    float* __restrict__ out)
{
    __shared__ float As[BM * ASTR];
    __shared__ float Bs[BK * BSTR];
    int row0 = blockIdx.y * BM;
    int col0 = blockIdx.x * BN;

    float acc[2][4][4];
#pragma unroll
    for (int m = 0; m < 2; m++)
#pragma unroll
        for (int n = 0; n < 4; n++)
#pragma unroll
            for (int j = 0; j < 4; j++) acc[m][n][j] = 0.f;

    gemm_tf32_main<CH>(g_att, W, row0, col0, As, Bs, acc);

    int tid = threadIdx.x;
    int warp = tid >> 5, lane = tid & 31;
    int wr = warp >> 1, wc = warp & 1;
    int g = lane >> 2, la3 = lane & 3;

#pragma unroll
    for (int mr = 0; mr < 2; mr++) {
#pragma unroll
        for (int nr = 0; nr < 4; nr++) {
#pragma unroll
            for (int j = 0; j < 4; j++) {
                int row = row0 + wr * 32 + mr * 16 + g + ((j >> 1) << 3);
                int n   = col0 + wc * 32 + nr * 8 + la3 * 2 + (j & 1);
                out[(size_t)row * CH + n] = acc[mr][nr][j] + bias[n];
            }
        }
    }
}

// ---------------------------------------------------------------------------
// Attention (unchanged): one CTA per (b, w, h), 576 threads.
// ---------------------------------------------------------------------------
__global__ __launch_bounds__(576, 1) void attn_kernel(
    const float* __restrict__ mask, const float* __restrict__ bias_table,
    const int* __restrict__ pidx)
{
    extern __shared__ float sm[];
    float* sq = sm;
    float* sk = sq + NTOK * SQS;
    float* sv = sk + NTOK * SQS;
    float* S  = sv + NTOK * SVS;

    int tid = threadIdx.x;
    int h = blockIdx.x, w = blockIdx.y, b = blockIdx.z;

    size_t base = (((size_t)b * NW + w) * HEADS_ + h) * (NTOK * DH);
    const size_t seg = (size_t)(B_ * NW * HEADS_) * (NTOK * DH);
    const float* gq = g_qkv + base;
    const float* gk = gq + seg;
    const float* gv = gk + seg;

    for (int idx = tid; idx < NTOK * DH; idx += 576) {
        int r = idx >> 5, c = idx & 31;
        sq[r * SQS + c] = gq[idx];
        sk[r * SQS + c] = gk[idx];
        sv[r * SVS + c] = gv[idx];
    }
    __syncthreads();

    int tr = tid / 24;
    int tc = tid % 24;
    float acc[6][6];
#pragma unroll
    for (int i = 0; i < 6; i++)
#pragma unroll
        for (int j = 0; j < 6; j++) acc[i][j] = 0.f;

#pragma unroll 4
    for (int d = 0; d < DH; d++) {
        float a[6], kk[6];
#pragma unroll
        for (int u = 0; u < 6; u++) a[u]  = sq[(tr + 24 * u) * SQS + d];
#pragma unroll
        for (int u = 0; u < 6; u++) kk[u] = sk[(tc + 24 * u) * SQS + d];
#pragma unroll
        for (int i = 0; i < 6; i++)
#pragma unroll
            for (int j = 0; j < 6; j++) acc[i][j] += a[i] * kk[j];
    }

    const float scale = 0.17677669529663687f;
    const float* mrow = mask + (size_t)b * NTOK * NTOK;
#pragma unroll
    for (int ui = 0; ui < 6; ui++) {
        int gi = tr + 24 * ui;
#pragma unroll
        for (int uj = 0; uj < 6; uj++) {
            int gj = tc + 24 * uj;
            int p = pidx[gi * NTOK + gj];
            float bv = bias_table[(p * NW + w) * HEADS_ + h];
            S[gi * SSS + gj] = acc[ui][uj] * scale + bv + mrow[gi * NTOK + gj];
        }
    }
    __syncthreads();

    int warp = tid >> 5, lane = tid & 31;
    for (int r = warp; r < NTOK; r += 18) {
        float* Sr = S + r * SSS;
        float mx = -3.4e38f;
        for (int j = lane; j < NTOK; j += 32) mx = fmaxf(mx, Sr[j]);
#pragma unroll
        for (int o = 16; o > 0; o >>= 1)
            mx = fmaxf(mx, __shfl_xor_sync(0xffffffffu, mx, o));
        float s = 0.f;
        for (int j = lane; j < NTOK; j += 32) {
            float e = __expf(Sr[j] - mx);
            Sr[j] = e;
            s += e;
        }
#pragma unroll
        for (int o = 16; o > 0; o >>= 1)
            s += __shfl_xor_sync(0xffffffffu, s, o);
        float inv = 1.f / s;
        for (int j = lane; j < NTOK; j += 32) Sr[j] *= inv;
    }
    __syncthreads();

    int r  = tid >> 2;
    int d0 = (tid & 3) << 3;
    float o0 = 0.f, o1 = 0.f, o2 = 0.f, o3 = 0.f;
    float o4 = 0.f, o5 = 0.f, o6 = 0.f, o7 = 0.f;
#pragma unroll 4
    for (int j = 0; j < NTOK; j++) {
        float p = S[r * SSS + j];
        float4 v0 = *(const float4*)&sv[j * SVS + d0];
        float4 v1 = *(const float4*)&sv[j * SVS + d0 + 4];
        o0 += p * v0.x; o1 += p * v0.y; o2 += p * v0.z; o3 += p * v0.w;
        o4 += p * v1.x; o5 += p * v1.y; o6 += p * v1.z; o7 += p * v1.w;
    }
    float* op = g_att + ((((size_t)b * NW + w) * NTOK + r) * CH) + h * DH + d0;
    *(float4*)op       = make_float4(o0, o1, o2, o3);
    *(float4*)(op + 4) = make_float4(o4, o5, o6, o7);
}

// ---------------------------------------------------------------------------
extern "C" void kernel_launch(void* const* d_in, const int* in_sizes, int n_in,
                              void* d_out, int out_size)
{
    const float* x          = (const float*)d_in[0];
    const float* mask       = (const float*)d_in[1];
    const float* w_qkv      = (const float*)d_in[2];
    const float* b_qkv      = (const float*)d_in[3];
    const float* w_proj     = (const float*)d_in[4];
    const float* b_proj     = (const float*)d_in[5];
    const float* bias_table = (const float*)d_in[6];
    const int*   pidx       = (const int*)d_in[7];
    float* out = (float*)d_out;

    const size_t smem_bytes =
        (size_t)(NTOK * SQS * 2 + NTOK * SVS + NTOK * SSS) * sizeof(float);
    cudaFuncSetAttribute(attn_kernel,
                         cudaFuncAttributeMaxDynamicSharedMemorySize,
                         (int)smem_bytes);

    // 1) QKV projection: M=138240, N=576. N-tiles on x for A reuse in L2.
    qkv_gemm_mma<<<dim3(9, 1080), 256>>>(x, w_qkv, b_qkv);

    // 2) Fused window attention
    attn_kernel<<<dim3(HEADS_, NW, B_), 576, smem_bytes>>>(mask, bias_table, pidx);

    // 3) Output projection: N=192
    proj_gemm_mma<<<dim3(3, 1080), 256>>>(w_proj, b_proj, out);
}